// round 3
// baseline (speedup 1.0000x reference)
#include <cuda_runtime.h>
#include <math.h>

#define DD 31
#define DIMV 32
#define MARGIN 0.85f

#define ASU64(x)  (*reinterpret_cast<unsigned long long*>(&(x)))
#define ASU64C(x) (*reinterpret_cast<const unsigned long long*>(&(x)))

// ---- packed fp32x2 ops (Blackwell sm_103a; ptxas never auto-fuses these) ----
__device__ __forceinline__ float2 ffma2(float2 a, float2 b, float2 c) {
    float2 d;
    asm("fma.rn.f32x2 %0, %1, %2, %3;"
        : "=l"(ASU64(d)) : "l"(ASU64C(a)), "l"(ASU64C(b)), "l"(ASU64C(c)));
    return d;
}
__device__ __forceinline__ float2 fadd2(float2 a, float2 b) {
    float2 d;
    asm("add.rn.f32x2 %0, %1, %2;" : "=l"(ASU64(d)) : "l"(ASU64C(a)), "l"(ASU64C(b)));
    return d;
}
__device__ __forceinline__ float2 fsub2(float2 a, float2 b) {
    float2 d;
    asm("sub.rn.f32x2 %0, %1, %2;" : "=l"(ASU64(d)) : "l"(ASU64C(a)), "l"(ASU64C(b)));
    return d;
}
__device__ __forceinline__ float2 fmul2(float2 a, float2 b) {
    float2 d;
    asm("mul.rn.f32x2 %0, %1, %2;" : "=l"(ASU64(d)) : "l"(ASU64C(a)), "l"(ASU64C(b)));
    return d;
}

// volatile LDS.128 — prevents ptxas CSE'ing the row between dot & update passes
__device__ __forceinline__ float4 lds128v(unsigned addr) {
    float4 v;
    asm volatile("ld.shared.v4.f32 {%0,%1,%2,%3}, [%4];"
                 : "=f"(v.x), "=f"(v.y), "=f"(v.z), "=f"(v.w) : "r"(addr));
    return v;
}

__device__ __forceinline__ float gelu_exact(float x) {
    return 0.5f * x * (1.0f + erff(x * 0.70710678118654752440f));
}

__device__ __forceinline__ float warp_sum(float v) {
#pragma unroll
    for (int o = 16; o; o >>= 1) v += __shfl_xor_sync(0xffffffffu, v, o);
    return v;
}

__global__ __launch_bounds__(128, 4)
void hypernet_kernel(const int* __restrict__ g_u, const int* __restrict__ g_r,
                     const int* __restrict__ g_v, const float* __restrict__ emb,
                     const float* __restrict__ bias_head, const float* __restrict__ bias_tail,
                     const float* __restrict__ head_rot_w, const float* __restrict__ head_boost_w,
                     const float* __restrict__ tail_rot_w, const float* __restrict__ tail_boost_w,
                     float* __restrict__ out, int N) {
    // tail table pre-duplicated for packed math: [i][j] = {w_j, w_j}; [i][31] = {-2/n2, -2/n2}
    __shared__ __align__(16) float2 s_wt2[DD][DIMV];
    __shared__ __align__(16) float  s_wh[DD][DIMV];   // head table (scalar, warp-0 only)
    __shared__ __align__(16) float2 s_th2[DIMV];      // s_th2[j] = {th[j+1], th[j+1]}, j=0..30
    __shared__ __align__(16) float2 s_ro2[DIMV];      // {ro_j, ro_j}, [31]={0,0}
    __shared__ float s_par[4];                        // zeta_t, coef_t, tanh(bias_head[u]), th[0]

    const int b    = blockIdx.x;
    const int tid  = threadIdx.x;
    const int lane = tid & 31;
    const int wid  = tid >> 5;
    const int rb   = g_r[b];

    // ---------------- Phase A: gelu both rotation tables into shared ----------------
    const float* hw = head_rot_w + (long)rb * (DD * DD);
    const float* tw = tail_rot_w + (long)rb * (DD * DD);
    for (int k = tid; k < DD * DD; k += blockDim.x) {
        int i = k / DD, j = k - i * DD;
        s_wh[i][j] = gelu_exact(hw[k]);
        float gt = gelu_exact(tw[k]);
        s_wt2[i][j] = make_float2(gt, gt);
    }
    __syncthreads();

    // ---------------- Phase A2: norms, tail boost, head bias ----------------
    if (wid == 0) {
#pragma unroll 1
        for (int i = 0; i < DD; i++) {
            float w  = (lane < DD) ? s_wt2[i][lane].x : 0.f;
            float n2 = warp_sum(w * w);
            if (lane == 0) { float s = -2.0f / n2; s_wt2[i][DD] = make_float2(s, s); }
        }
    } else if (wid == 1) {
#pragma unroll 1
        for (int i = 0; i < DD; i++) {
            float w  = (lane < DD) ? s_wh[i][lane] : 0.f;
            float n2 = warp_sum(w * w);
            if (lane == 0) s_wh[i][DD] = 2.0f / n2;
        }
    } else if (wid == 2) {
        float ro = (lane < DD) ? tanhf(tail_boost_w[(long)rb * DD + lane]) * (1.0f / DIMV) : 0.f;
        s_ro2[lane] = make_float2(ro, ro);   // lane 31 writes {0,0}
        float v2   = warp_sum(ro * ro);
        float zeta = 1.0f / (sqrtf(1.0f - v2) + 1e-8f);
        if (lane == 0) { s_par[0] = zeta; s_par[1] = (zeta - 1.0f) / (v2 + 1e-9f); }
    } else if (wid == 3) {
        if (lane == 0) s_par[2] = tanhf(bias_head[g_u[b]]);
    }
    __syncthreads();

    // ---------------- Phase B: warp 0 transforms the head vector ----------------
    if (wid == 0) {
        float c = emb[(long)g_u[b] * DIMV + lane];  // lane j = component j (lane 0 = time)
#pragma unroll 1
        for (int i = 0; i < DD; i++) {
            float w   = (lane >= 1) ? s_wh[i][lane - 1] : 0.f;
            float sc  = s_wh[i][DD];
            float dot = warp_sum(c * w);
            c = fmaf(-sc * dot, w, c);
        }
        float rh   = (lane >= 1) ? tanhf(head_boost_w[(long)rb * DD + lane - 1]) * (1.0f / DIMV) : 0.f;
        float v2   = warp_sum(rh * rh);
        float zeta = 1.0f / (sqrtf(1.0f - v2) + 1e-8f);
        float coef = (zeta - 1.0f) / (v2 + 1e-9f);
        float tval = __shfl_sync(0xffffffffu, c, 0);
        float dotb = warp_sum(c * rh);
        float res;
        if (lane == 0) res = zeta * tval - zeta * dotb;
        else           res = -zeta * tval * rh + c + coef * rh * dotb;
        if (lane == 0) s_par[3] = res;
        else           s_th2[lane - 1] = make_float2(res, res);
    }
    __syncthreads();

    const float zt  = s_par[0];
    const float ct  = s_par[1];
    const float tbh = s_par[2];
    const float th0 = s_par[3];
    const float2 zt2  = make_float2(zt, zt);
    const float2 nzt2 = make_float2(-zt, -zt);
    const float2 ct2  = make_float2(ct, ct);
    const float2 th02 = make_float2(th0, th0);
    const float2 zero = make_float2(0.f, 0.f);

    const unsigned wt_base = (unsigned)__cvta_generic_to_shared(&s_wt2[0][0]);

    // ---------------- Phase C: each thread handles TWO tail vectors (packed f32x2) ----
    for (int n = 2 * tid; n < N; n += 2 * blockDim.x) {
        const int2 vv = *(const int2*)(g_v + (long)b * N + n);

        float2 x0p, xp[DD];
        {
            const float4* ea = (const float4*)(emb + (long)vv.x * DIMV);
            const float4* eb = (const float4*)(emb + (long)vv.y * DIMV);
            float4 A = ea[0], Bq = eb[0];
            x0p   = make_float2(A.x, Bq.x);
            xp[0] = make_float2(A.y, Bq.y);
            xp[1] = make_float2(A.z, Bq.z);
            xp[2] = make_float2(A.w, Bq.w);
#pragma unroll
            for (int q = 1; q < 8; q++) {
                A = ea[q]; Bq = eb[q];
                xp[4 * q - 1] = make_float2(A.x, Bq.x);
                xp[4 * q + 0] = make_float2(A.y, Bq.y);
                xp[4 * q + 1] = make_float2(A.z, Bq.z);
                xp[4 * q + 2] = make_float2(A.w, Bq.w);
            }
        }
        const float bta = bias_tail[vv.x];
        const float btb = bias_tail[vv.y];

        // 31 Householder reflections, both vectors per instruction
#pragma unroll 1
        for (int i = 0; i < DD; i++) {
            const unsigned row = wt_base + (unsigned)i * (DIMV * 8);
            float2 a0 = zero, a1 = zero, a2 = zero, a3 = zero;
#pragma unroll
            for (int q = 0; q < 7; q++) {
                float4 wA = lds128v(row + 32 * q);
                float4 wB = lds128v(row + 32 * q + 16);
                a0 = ffma2(xp[4 * q + 0], make_float2(wA.x, wA.y), a0);
                a1 = ffma2(xp[4 * q + 1], make_float2(wA.z, wA.w), a1);
                a2 = ffma2(xp[4 * q + 2], make_float2(wB.x, wB.y), a2);
                a3 = ffma2(xp[4 * q + 3], make_float2(wB.z, wB.w), a3);
            }
            float4 wA = lds128v(row + 32 * 7);
            float4 wB = lds128v(row + 32 * 7 + 16);
            a0 = ffma2(xp[28], make_float2(wA.x, wA.y), a0);
            a1 = ffma2(xp[29], make_float2(wA.z, wA.w), a1);
            a2 = ffma2(xp[30], make_float2(wB.x, wB.y), a2);
            const float2 nsc = make_float2(wB.z, wB.w);           // {-2/n2, -2/n2}
            const float2 dot = fadd2(fadd2(a0, a1), fadd2(a2, a3));
            const float2 g   = fmul2(nsc, dot);                   // already negated

#pragma unroll
            for (int q = 0; q < 7; q++) {
                float4 uA = lds128v(row + 32 * q);
                float4 uB = lds128v(row + 32 * q + 16);
                xp[4 * q + 0] = ffma2(g, make_float2(uA.x, uA.y), xp[4 * q + 0]);
                xp[4 * q + 1] = ffma2(g, make_float2(uA.z, uA.w), xp[4 * q + 1]);
                xp[4 * q + 2] = ffma2(g, make_float2(uB.x, uB.y), xp[4 * q + 2]);
                xp[4 * q + 3] = ffma2(g, make_float2(uB.z, uB.w), xp[4 * q + 3]);
            }
            float4 uA = lds128v(row + 32 * 7);
            float4 uB = lds128v(row + 32 * 7 + 16);
            xp[28] = ffma2(g, make_float2(uA.x, uA.y), xp[28]);
            xp[29] = ffma2(g, make_float2(uA.z, uA.w), xp[29]);
            xp[30] = ffma2(g, make_float2(uB.x, uB.y), xp[30]);
        }

        // ---- tail boost + Lorentz distance (packed) ----
        const float4* rp = (const float4*)(&s_ro2[0]);
        float2 a0 = zero, a1 = zero, a2 = zero, a3 = zero;
#pragma unroll
        for (int q = 0; q < 7; q++) {
            float4 rA = rp[2 * q], rB = rp[2 * q + 1];
            a0 = ffma2(xp[4 * q + 0], make_float2(rA.x, rA.y), a0);
            a1 = ffma2(xp[4 * q + 1], make_float2(rA.z, rA.w), a1);
            a2 = ffma2(xp[4 * q + 2], make_float2(rB.x, rB.y), a2);
            a3 = ffma2(xp[4 * q + 3], make_float2(rB.z, rB.w), a3);
        }
        {
            float4 rA = rp[14], rB = rp[15];
            a0 = ffma2(xp[28], make_float2(rA.x, rA.y), a0);
            a1 = ffma2(xp[29], make_float2(rA.z, rA.w), a1);
            a2 = ffma2(xp[30], make_float2(rB.x, rB.y), a2);
        }
        const float2 dotb = fadd2(fadd2(a0, a1), fadd2(a2, a3));

        const float2 nx0 = fmul2(zt2, fsub2(x0p, dotb));
        const float2 d0  = fsub2(nx0, th02);
        const float2 mzt = fmul2(nzt2, x0p);       // -zeta * t
        const float2 cd  = fmul2(ct2, dotb);       // coef * dot

        const float4* tp = (const float4*)(&s_th2[0]);
        float2 acc = zero;
#pragma unroll
        for (int q = 0; q < 7; q++) {
            float4 rA = rp[2 * q], rB = rp[2 * q + 1];
            float4 tA = tp[2 * q], tB = tp[2 * q + 1];
            float2 ro0 = make_float2(rA.x, rA.y), ro1 = make_float2(rA.z, rA.w);
            float2 ro2 = make_float2(rB.x, rB.y), ro3 = make_float2(rB.z, rB.w);
            float2 x0_ = ffma2(cd, ro0, ffma2(mzt, ro0, xp[4 * q + 0]));
            float2 x1_ = ffma2(cd, ro1, ffma2(mzt, ro1, xp[4 * q + 1]));
            float2 x2_ = ffma2(cd, ro2, ffma2(mzt, ro2, xp[4 * q + 2]));
            float2 x3_ = ffma2(cd, ro3, ffma2(mzt, ro3, xp[4 * q + 3]));
            float2 dj0 = fsub2(x0_, make_float2(tA.x, tA.y));
            float2 dj1 = fsub2(x1_, make_float2(tA.z, tA.w));
            float2 dj2 = fsub2(x2_, make_float2(tB.x, tB.y));
            float2 dj3 = fsub2(x3_, make_float2(tB.z, tB.w));
            acc = ffma2(dj0, dj0, acc);
            acc = ffma2(dj1, dj1, acc);
            acc = ffma2(dj2, dj2, acc);
            acc = ffma2(dj3, dj3, acc);
        }
        {
            float4 rA = rp[14], rB = rp[15];
            float4 tA = tp[14], tB = tp[15];
            float2 ro0 = make_float2(rA.x, rA.y), ro1 = make_float2(rA.z, rA.w);
            float2 ro2 = make_float2(rB.x, rB.y);
            float2 x0_ = ffma2(cd, ro0, ffma2(mzt, ro0, xp[28]));
            float2 x1_ = ffma2(cd, ro1, ffma2(mzt, ro1, xp[29]));
            float2 x2_ = ffma2(cd, ro2, ffma2(mzt, ro2, xp[30]));
            float2 dj0 = fsub2(x0_, make_float2(tA.x, tA.y));
            float2 dj1 = fsub2(x1_, make_float2(tA.z, tA.w));
            float2 dj2 = fsub2(x2_, make_float2(tB.x, tB.y));
            acc = ffma2(dj0, dj0, acc);
            acc = ffma2(dj1, dj1, acc);
            acc = ffma2(dj2, dj2, acc);
        }

        // mkv = (acc + d0^2) - 2*d0^2 = acc - d0^2
        const float2 mkv = fsub2(acc, fmul2(d0, d0));

        float rx = MARGIN - mkv.x + tbh + tanhf(bta);
        float ry = MARGIN - mkv.y + tbh + tanhf(btb);
        *(float2*)(out + (long)b * N + n) = make_float2(rx, ry);
    }
}

extern "C" void kernel_launch(void* const* d_in, const int* in_sizes, int n_in,
                              void* d_out, int out_size) {
    const int*   u   = (const int*)d_in[0];
    const int*   r   = (const int*)d_in[1];
    const int*   v   = (const int*)d_in[2];
    const float* emb = (const float*)d_in[3];
    const float* bh  = (const float*)d_in[4];
    const float* bt  = (const float*)d_in[5];
    const float* hrw = (const float*)d_in[6];
    const float* hbw = (const float*)d_in[7];
    const float* trw = (const float*)d_in[8];
    const float* tbw = (const float*)d_in[9];
    float* out = (float*)d_out;

    const int B = in_sizes[0];
    const int N = in_sizes[2] / B;

    hypernet_kernel<<<B, 128>>>(u, r, v, emb, bh, bt, hrw, hbw, trw, tbw, out, N);
}